// round 1
// baseline (speedup 1.0000x reference)
#include <cuda_runtime.h>
#include <math.h>

#define B_    2
#define T_    4096
#define C_    768
#define H_    12
#define D_    64
#define QKV3  2304

// Scratch (allocation-free: __device__ globals)
__device__ float g_xn[(size_t)B_ * T_ * C_];      // 25.2 MB
__device__ float g_qkv[(size_t)B_ * T_ * QKV3];   // 75.5 MB
__device__ float g_attn[(size_t)B_ * T_ * C_];    // 25.2 MB

// ---------------------------------------------------------------------------
// LayerNorm over last dim (C=768). One block per row, 256 threads, 3 elems/thr.
// ---------------------------------------------------------------------------
__global__ void __launch_bounds__(256) ln_kernel(
    const float* __restrict__ x, const float* __restrict__ gamma,
    const float* __restrict__ beta, float* __restrict__ out)
{
    int row = blockIdx.x;
    int tid = threadIdx.x;
    const float* xr = x + (size_t)row * C_;
    float v0 = xr[tid], v1 = xr[tid + 256], v2 = xr[tid + 512];
    float s  = v0 + v1 + v2;
    float ss = v0 * v0 + v1 * v1 + v2 * v2;
    #pragma unroll
    for (int o = 16; o > 0; o >>= 1) {
        s  += __shfl_xor_sync(0xffffffffu, s,  o);
        ss += __shfl_xor_sync(0xffffffffu, ss, o);
    }
    __shared__ float sh_s[8], sh_q[8];
    int w = tid >> 5;
    if ((tid & 31) == 0) { sh_s[w] = s; sh_q[w] = ss; }
    __syncthreads();
    float S = 0.f, Q = 0.f;
    #pragma unroll
    for (int i = 0; i < 8; i++) { S += sh_s[i]; Q += sh_q[i]; }
    float mean = S * (1.0f / C_);
    float var  = Q * (1.0f / C_) - mean * mean;
    float rstd = rsqrtf(var + 1e-5f);
    float* orow = out + (size_t)row * C_;
    orow[tid]       = (v0 - mean) * rstd * gamma[tid]       + beta[tid];
    orow[tid + 256] = (v1 - mean) * rstd * gamma[tid + 256] + beta[tid + 256];
    orow[tid + 512] = (v2 - mean) * rstd * gamma[tid + 512] + beta[tid + 512];
}

// ---------------------------------------------------------------------------
// SGEMM NT: C[m,n] = sum_k A[m,k] * B[n,k] (+ bias[n]).
// 128x128 tile, BK=8, 256 threads, 8x8 microtile. M,N,K multiples of 128/8.
// ---------------------------------------------------------------------------
__global__ void __launch_bounds__(256) sgemm_nt(
    const float* __restrict__ A, const float* __restrict__ Bm,
    const float* __restrict__ bias, float* __restrict__ Cm,
    int M, int N, int K)
{
    __shared__ float As[8][128];
    __shared__ float Bs[8][128];
    int tid = threadIdx.x;
    int n0 = blockIdx.x * 128, m0 = blockIdx.y * 128;
    int tx = tid & 15, ty = tid >> 4;
    int lr = tid >> 1, lc = (tid & 1) * 4;
    const float* Ap = A  + (size_t)(m0 + lr) * K + lc;
    const float* Bp = Bm + (size_t)(n0 + lr) * K + lc;

    float acc[8][8];
    #pragma unroll
    for (int i = 0; i < 8; i++)
        #pragma unroll
        for (int j = 0; j < 8; j++) acc[i][j] = 0.f;

    for (int k0 = 0; k0 < K; k0 += 8) {
        float4 a = *(const float4*)(Ap + k0);
        float4 b = *(const float4*)(Bp + k0);
        As[lc + 0][lr] = a.x; As[lc + 1][lr] = a.y;
        As[lc + 2][lr] = a.z; As[lc + 3][lr] = a.w;
        Bs[lc + 0][lr] = b.x; Bs[lc + 1][lr] = b.y;
        Bs[lc + 2][lr] = b.z; Bs[lc + 3][lr] = b.w;
        __syncthreads();
        #pragma unroll
        for (int k = 0; k < 8; k++) {
            float4 a0 = *(const float4*)&As[k][ty * 8];
            float4 a1 = *(const float4*)&As[k][ty * 8 + 4];
            float4 b0 = *(const float4*)&Bs[k][tx * 8];
            float4 b1 = *(const float4*)&Bs[k][tx * 8 + 4];
            float ar[8] = {a0.x, a0.y, a0.z, a0.w, a1.x, a1.y, a1.z, a1.w};
            float br[8] = {b0.x, b0.y, b0.z, b0.w, b1.x, b1.y, b1.z, b1.w};
            #pragma unroll
            for (int i = 0; i < 8; i++)
                #pragma unroll
                for (int j = 0; j < 8; j++)
                    acc[i][j] = fmaf(ar[i], br[j], acc[i][j]);
        }
        __syncthreads();
    }

    #pragma unroll
    for (int i = 0; i < 8; i++) {
        int row = m0 + ty * 8 + i;
        float* cp = Cm + (size_t)row * N + n0 + tx * 8;
        float bj[8];
        #pragma unroll
        for (int j = 0; j < 8; j++)
            bj[j] = acc[i][j] + (bias ? bias[n0 + tx * 8 + j] : 0.f);
        *(float4*)cp       = make_float4(bj[0], bj[1], bj[2], bj[3]);
        *(float4*)(cp + 4) = make_float4(bj[4], bj[5], bj[6], bj[7]);
    }
}

// ---------------------------------------------------------------------------
// Flash attention fp32 with block-causal frame mask.
// Q-tile = 64 rows; frame boundary (256) is a multiple of 64 -> no per-element
// masking, just bound key loop at kmax = (frame+1)*256.
// Block: 256 threads as 16x16, each owns a 4x4 microtile of the 64x64 S/O tile.
// ---------------------------------------------------------------------------
#define SMSTR 68  // padded stride (float), %4==0 for aligned float4, odd/4 for banks

__global__ void __launch_bounds__(256) attn_kernel(
    const float* __restrict__ qkv, float* __restrict__ out)
{
    extern __shared__ float sm[];
    float* QsT = sm;                  // [d][r]   64 x SMSTR (pre-scaled Q)
    float* KsT = QsT + 64 * SMSTR;    // [d][s]
    float* Vs  = KsT + 64 * SMSTR;    // [s][d]
    float* PsT = Vs  + 64 * SMSTR;    // [s][r]

    int tid = threadIdx.x;
    int qt  = blockIdx.x;
    int bh  = blockIdx.y;
    int b = bh / H_, h = bh % H_;
    int r0 = qt * 64;
    const float scale = 0.125f;  // 1/sqrt(64)
    const float* qbase = qkv + (size_t)(b * T_) * QKV3 + h * D_;

    // Load Q tile transposed (d-major) with scale folded in
    {
        int r  = tid >> 2;
        int c0 = (tid & 3) * 16;
        const float* qp = qbase + (size_t)(r0 + r) * QKV3 + c0;
        #pragma unroll
        for (int j = 0; j < 4; j++) {
            float4 q4 = *(const float4*)(qp + j * 4);
            QsT[(c0 + j * 4 + 0) * SMSTR + r] = q4.x * scale;
            QsT[(c0 + j * 4 + 1) * SMSTR + r] = q4.y * scale;
            QsT[(c0 + j * 4 + 2) * SMSTR + r] = q4.z * scale;
            QsT[(c0 + j * 4 + 3) * SMSTR + r] = q4.w * scale;
        }
    }

    int tx = tid & 15, ty = tid >> 4;
    float m[4], l[4], acc[4][4];
    #pragma unroll
    for (int i = 0; i < 4; i++) {
        m[i] = -INFINITY; l[i] = 0.f;
        #pragma unroll
        for (int j = 0; j < 4; j++) acc[i][j] = 0.f;
    }

    int nkt = ((r0 >> 8) + 1) << 2;  // kmax/64 = (frame+1)*4

    for (int kt = 0; kt < nkt; kt++) {
        __syncthreads();  // prior iter's KsT/Vs/PsT reads must finish
        // Load K (transposed) and V tiles
        {
            int r  = tid >> 2;
            int c0 = (tid & 3) * 16;
            const float* kp = qbase + 768  + (size_t)(kt * 64 + r) * QKV3 + c0;
            const float* vp = qbase + 1536 + (size_t)(kt * 64 + r) * QKV3 + c0;
            #pragma unroll
            for (int j = 0; j < 4; j++) {
                float4 k4 = *(const float4*)(kp + j * 4);
                KsT[(c0 + j * 4 + 0) * SMSTR + r] = k4.x;
                KsT[(c0 + j * 4 + 1) * SMSTR + r] = k4.y;
                KsT[(c0 + j * 4 + 2) * SMSTR + r] = k4.z;
                KsT[(c0 + j * 4 + 3) * SMSTR + r] = k4.w;
                float4 v4 = *(const float4*)(vp + j * 4);
                *(float4*)&Vs[r * SMSTR + c0 + j * 4] = v4;
            }
        }
        __syncthreads();

        // S = (Q*scale) K^T, 4x4 per thread
        float s[4][4];
        #pragma unroll
        for (int i = 0; i < 4; i++)
            #pragma unroll
            for (int j = 0; j < 4; j++) s[i][j] = 0.f;
        #pragma unroll 8
        for (int d = 0; d < 64; d++) {
            float4 qa = *(const float4*)&QsT[d * SMSTR + ty * 4];
            float4 kb = *(const float4*)&KsT[d * SMSTR + tx * 4];
            float qr[4] = {qa.x, qa.y, qa.z, qa.w};
            float kr[4] = {kb.x, kb.y, kb.z, kb.w};
            #pragma unroll
            for (int i = 0; i < 4; i++)
                #pragma unroll
                for (int j = 0; j < 4; j++)
                    s[i][j] = fmaf(qr[i], kr[j], s[i][j]);
        }

        // Online softmax (reduce across the 16 tx lanes; replicated stats)
        #pragma unroll
        for (int i = 0; i < 4; i++) {
            float tm = fmaxf(fmaxf(s[i][0], s[i][1]), fmaxf(s[i][2], s[i][3]));
            #pragma unroll
            for (int o = 1; o < 16; o <<= 1)
                tm = fmaxf(tm, __shfl_xor_sync(0xffffffffu, tm, o));
            float nm = fmaxf(m[i], tm);
            float alpha = __expf(m[i] - nm);
            m[i] = nm;
            float p[4], rs = 0.f;
            #pragma unroll
            for (int j = 0; j < 4; j++) { p[j] = __expf(s[i][j] - nm); rs += p[j]; }
            #pragma unroll
            for (int o = 1; o < 16; o <<= 1)
                rs += __shfl_xor_sync(0xffffffffu, rs, o);
            l[i] = l[i] * alpha + rs;
            #pragma unroll
            for (int j = 0; j < 4; j++) {
                acc[i][j] *= alpha;
                PsT[(tx * 4 + j) * SMSTR + ty * 4 + i] = p[j];
            }
        }
        __syncthreads();

        // O += P V
        #pragma unroll 8
        for (int sI = 0; sI < 64; sI++) {
            float4 pa = *(const float4*)&PsT[sI * SMSTR + ty * 4];
            float4 vb = *(const float4*)&Vs[sI * SMSTR + tx * 4];
            float pr[4] = {pa.x, pa.y, pa.z, pa.w};
            float vr[4] = {vb.x, vb.y, vb.z, vb.w};
            #pragma unroll
            for (int i = 0; i < 4; i++)
                #pragma unroll
                for (int j = 0; j < 4; j++)
                    acc[i][j] = fmaf(pr[i], vr[j], acc[i][j]);
        }
    }

    // Write normalized output: [B,T,H*D] layout
    #pragma unroll
    for (int i = 0; i < 4; i++) {
        float inv = 1.0f / l[i];
        int row = r0 + ty * 4 + i;
        float* op = out + ((size_t)(b * T_ + row)) * C_ + h * D_ + tx * 4;
        *(float4*)op = make_float4(acc[i][0] * inv, acc[i][1] * inv,
                                   acc[i][2] * inv, acc[i][3] * inv);
    }
}

// ---------------------------------------------------------------------------
extern "C" void kernel_launch(void* const* d_in, const int* in_sizes, int n_in,
                              void* d_out, int out_size)
{
    const float* x     = (const float*)d_in[0];
    const float* gamma = (const float*)d_in[1];
    const float* beta  = (const float*)d_in[2];
    const float* w_qkv = (const float*)d_in[3];
    const float* w_out = (const float*)d_in[4];
    const float* b_out = (const float*)d_in[5];
    float* out = (float*)d_out;

    float *xn, *qkv, *attn;
    cudaGetSymbolAddress((void**)&xn,   g_xn);
    cudaGetSymbolAddress((void**)&qkv,  g_qkv);
    cudaGetSymbolAddress((void**)&attn, g_attn);

    // 1) LayerNorm
    ln_kernel<<<B_ * T_, 256>>>(x, gamma, beta, xn);

    // 2) QKV projection: [8192,768] x [2304,768]^T -> [8192,2304]
    sgemm_nt<<<dim3(QKV3 / 128, (B_ * T_) / 128), 256>>>(
        xn, w_qkv, nullptr, qkv, B_ * T_, QKV3, C_);

    // 3) Flash attention (block-causal by frame)
    const int attn_smem = 4 * 64 * SMSTR * (int)sizeof(float);  // 69632 B
    cudaFuncSetAttribute(attn_kernel,
                         cudaFuncAttributeMaxDynamicSharedMemorySize, attn_smem);
    attn_kernel<<<dim3(T_ / 64, B_ * H_), 256, attn_smem>>>(qkv, attn);

    // 4) Output projection + bias: [8192,768] x [768,768]^T -> [8192,768]
    sgemm_nt<<<dim3(C_ / 128, (B_ * T_) / 128), 256>>>(
        attn, w_out, b_out, out, B_ * T_, C_, C_);
}

// round 2
// speedup vs baseline: 1.5403x; 1.5403x over previous
#include <cuda_runtime.h>
#include <math.h>
#include <stdint.h>

#define B_    2
#define T_    4096
#define C_    768
#define H_    12
#define D_    64
#define QKV3  2304

// Scratch (allocation-free: __device__ globals)
__device__ float g_xn[(size_t)B_ * T_ * C_];
__device__ float g_qkv[(size_t)B_ * T_ * QKV3];
__device__ float g_attn[(size_t)B_ * T_ * C_];

// ---------------------------------------------------------------------------
// Helpers: tf32 conversion + m16n8k8 tf32 mma
// ---------------------------------------------------------------------------
__device__ __forceinline__ uint32_t f2tf(float x) {
    uint32_t r;
    asm("cvt.rna.tf32.f32 %0, %1;" : "=r"(r) : "f"(x));
    return r;
}

__device__ __forceinline__ void mma8(float* d, const uint32_t* a, const uint32_t* b) {
    asm volatile(
        "mma.sync.aligned.m16n8k8.row.col.f32.tf32.tf32.f32 "
        "{%0,%1,%2,%3}, {%4,%5,%6,%7}, {%8,%9}, {%0,%1,%2,%3};\n"
        : "+f"(d[0]), "+f"(d[1]), "+f"(d[2]), "+f"(d[3])
        : "r"(a[0]), "r"(a[1]), "r"(a[2]), "r"(a[3]), "r"(b[0]), "r"(b[1]));
}

// ---------------------------------------------------------------------------
// LayerNorm over last dim (C=768). One block per row.
// ---------------------------------------------------------------------------
__global__ void __launch_bounds__(256) ln_kernel(
    const float* __restrict__ x, const float* __restrict__ gamma,
    const float* __restrict__ beta, float* __restrict__ out)
{
    int row = blockIdx.x;
    int tid = threadIdx.x;
    const float* xr = x + (size_t)row * C_;
    float v0 = xr[tid], v1 = xr[tid + 256], v2 = xr[tid + 512];
    float s  = v0 + v1 + v2;
    float ss = v0 * v0 + v1 * v1 + v2 * v2;
    #pragma unroll
    for (int o = 16; o > 0; o >>= 1) {
        s  += __shfl_xor_sync(0xffffffffu, s,  o);
        ss += __shfl_xor_sync(0xffffffffu, ss, o);
    }
    __shared__ float sh_s[8], sh_q[8];
    int w = tid >> 5;
    if ((tid & 31) == 0) { sh_s[w] = s; sh_q[w] = ss; }
    __syncthreads();
    float S = 0.f, Q = 0.f;
    #pragma unroll
    for (int i = 0; i < 8; i++) { S += sh_s[i]; Q += sh_q[i]; }
    float mean = S * (1.0f / C_);
    float var  = Q * (1.0f / C_) - mean * mean;
    float rstd = rsqrtf(var + 1e-5f);
    float* orow = out + (size_t)row * C_;
    orow[tid]       = (v0 - mean) * rstd * gamma[tid]       + beta[tid];
    orow[tid + 256] = (v1 - mean) * rstd * gamma[tid + 256] + beta[tid + 256];
    orow[tid + 512] = (v2 - mean) * rstd * gamma[tid + 512] + beta[tid + 512];
}

// ---------------------------------------------------------------------------
// GEMM NT via 3xTF32 mma: C[m,n] = sum_k A[m,k]*B[n,k] (+bias[n]), fp32-accurate.
// Block 128x128, BK=16, 256 threads (8 warps, 2x4), warp tile 64x32.
// ---------------------------------------------------------------------------
#define GSTR 136

__global__ void __launch_bounds__(256) gemm_tf32x3(
    const float* __restrict__ A, const float* __restrict__ Bm,
    const float* __restrict__ bias, float* __restrict__ Cm,
    int M, int N, int K)
{
    __shared__ float Ah[16][GSTR], Al[16][GSTR], Bh[16][GSTR], Bl[16][GSTR];
    int tid  = threadIdx.x;
    int lane = tid & 31, warp = tid >> 5;
    int lr = lane >> 2, lc = lane & 3;
    int wm = (warp & 1) * 64, wn = (warp >> 1) * 32;
    int m0 = blockIdx.y * 128, n0 = blockIdx.x * 128;
    int lrow = tid >> 1, lk = (tid & 1) * 8;
    const float* Ap = A  + (size_t)(m0 + lrow) * K + lk;
    const float* Bp = Bm + (size_t)(n0 + lrow) * K + lk;

    float acc[4][4][4];
    #pragma unroll
    for (int i = 0; i < 4; i++)
        #pragma unroll
        for (int j = 0; j < 4; j++)
            #pragma unroll
            for (int r = 0; r < 4; r++) acc[i][j][r] = 0.f;

    for (int k0 = 0; k0 < K; k0 += 16) {
        float4 a0 = *(const float4*)(Ap + k0);
        float4 a1 = *(const float4*)(Ap + k0 + 4);
        float4 b0 = *(const float4*)(Bp + k0);
        float4 b1 = *(const float4*)(Bp + k0 + 4);
        float av[8] = {a0.x, a0.y, a0.z, a0.w, a1.x, a1.y, a1.z, a1.w};
        float bv[8] = {b0.x, b0.y, b0.z, b0.w, b1.x, b1.y, b1.z, b1.w};
        #pragma unroll
        for (int j = 0; j < 8; j++) {
            uint32_t h = f2tf(av[j]);
            Ah[lk + j][lrow] = __uint_as_float(h);
            Al[lk + j][lrow] = __uint_as_float(f2tf(av[j] - __uint_as_float(h)));
            uint32_t g = f2tf(bv[j]);
            Bh[lk + j][lrow] = __uint_as_float(g);
            Bl[lk + j][lrow] = __uint_as_float(f2tf(bv[j] - __uint_as_float(g)));
        }
        __syncthreads();
        #pragma unroll
        for (int ks = 0; ks < 16; ks += 8) {
            uint32_t ra[4][4], rb[4][2];
            uint32_t la[4][4], lb[4][2];
            #pragma unroll
            for (int mi = 0; mi < 4; mi++) {
                int mb = wm + mi * 16;
                ra[mi][0] = __float_as_uint(Ah[ks + lc][mb + lr]);
                ra[mi][1] = __float_as_uint(Ah[ks + lc][mb + 8 + lr]);
                ra[mi][2] = __float_as_uint(Ah[ks + 4 + lc][mb + lr]);
                ra[mi][3] = __float_as_uint(Ah[ks + 4 + lc][mb + 8 + lr]);
                la[mi][0] = __float_as_uint(Al[ks + lc][mb + lr]);
                la[mi][1] = __float_as_uint(Al[ks + lc][mb + 8 + lr]);
                la[mi][2] = __float_as_uint(Al[ks + 4 + lc][mb + lr]);
                la[mi][3] = __float_as_uint(Al[ks + 4 + lc][mb + 8 + lr]);
            }
            #pragma unroll
            for (int nj = 0; nj < 4; nj++) {
                int nb = wn + nj * 8;
                rb[nj][0] = __float_as_uint(Bh[ks + lc][nb + lr]);
                rb[nj][1] = __float_as_uint(Bh[ks + 4 + lc][nb + lr]);
                lb[nj][0] = __float_as_uint(Bl[ks + lc][nb + lr]);
                lb[nj][1] = __float_as_uint(Bl[ks + 4 + lc][nb + lr]);
            }
            #pragma unroll
            for (int mi = 0; mi < 4; mi++)
                #pragma unroll
                for (int nj = 0; nj < 4; nj++) {
                    mma8(acc[mi][nj], ra[mi], rb[nj]);
                    mma8(acc[mi][nj], la[mi], rb[nj]);
                    mma8(acc[mi][nj], ra[mi], lb[nj]);
                }
        }
        __syncthreads();
    }

    #pragma unroll
    for (int mi = 0; mi < 4; mi++)
        #pragma unroll
        for (int nj = 0; nj < 4; nj++) {
            int row = m0 + wm + mi * 16 + lr;
            int col = n0 + wn + nj * 8 + 2 * lc;
            float bb0 = bias ? bias[col]     : 0.f;
            float bb1 = bias ? bias[col + 1] : 0.f;
            float2 v0 = make_float2(acc[mi][nj][0] + bb0, acc[mi][nj][1] + bb1);
            float2 v1 = make_float2(acc[mi][nj][2] + bb0, acc[mi][nj][3] + bb1);
            *(float2*)(Cm + (size_t)row * N + col)       = v0;
            *(float2*)(Cm + (size_t)(row + 8) * N + col) = v1;
        }
}

// ---------------------------------------------------------------------------
// Flash attention, tf32 tensor-core path.
// Block = 128 threads (4 warps), q-tile 64 (warp owns 16 q-rows).
// K/V stored in smem in mma B-fragment order (one LDS.64 per operand);
// P staged per-warp in A-fragment order (one LDS.128 per k-step).
// Block-causal frame mask handled by key-loop bound; no per-element masking.
// ---------------------------------------------------------------------------
__global__ void __launch_bounds__(128) attn_tf32(
    const float* __restrict__ qkv, float* __restrict__ out)
{
    extern __shared__ float sm[];
    float* Kf = sm;            // 4096 floats
    float* Vf = sm + 4096;     // 4096 floats
    float* Pf = sm + 8192;     // 4096 floats (1024 per warp)

    int tid  = threadIdx.x;
    int lane = tid & 31, warp = tid >> 5;
    int lr = lane >> 2, lc = lane & 3;
    int qt = blockIdx.x, bh = blockIdx.y;
    int b = bh / H_, h = bh % H_;
    int r0 = qt * 64;
    const float* base = qkv + (size_t)b * T_ * QKV3 + h * D_;

    // ---- stage Q (scaled) raw into Kf/Vf region, then read A-fragments
    #pragma unroll
    for (int c = 0; c < 8; c++) {
        int rr = (tid >> 4) + c * 8;
        int cc = (tid & 15) * 4;
        float4 v = *(const float4*)(base + (size_t)(r0 + rr) * QKV3 + cc);
        v.x *= 0.125f; v.y *= 0.125f; v.z *= 0.125f; v.w *= 0.125f;
        *(float4*)&sm[rr * 68 + cc] = v;
    }
    __syncthreads();
    uint32_t qf[8][4];
    int q0w = warp * 16;
    #pragma unroll
    for (int ks = 0; ks < 8; ks++) {
        qf[ks][0] = f2tf(sm[(q0w + lr) * 68 + ks * 8 + lc]);
        qf[ks][1] = f2tf(sm[(q0w + 8 + lr) * 68 + ks * 8 + lc]);
        qf[ks][2] = f2tf(sm[(q0w + lr) * 68 + ks * 8 + 4 + lc]);
        qf[ks][3] = f2tf(sm[(q0w + 8 + lr) * 68 + ks * 8 + 4 + lc]);
    }
    __syncthreads();

    float o[8][4];
    #pragma unroll
    for (int nj = 0; nj < 8; nj++)
        #pragma unroll
        for (int r = 0; r < 4; r++) o[nj][r] = 0.f;
    float m0r = -INFINITY, m1r = -INFINITY, l0 = 0.f, l1 = 0.f;
    float* Pw = Pf + warp * 1024;

    int nkt = ((qt >> 2) + 1) << 2;  // (frame+1)*4 key tiles of 64

    for (int kt = 0; kt < nkt; kt++) {
        // ---- load K,V tile into fragment-ordered smem (tf32-converted)
        #pragma unroll
        for (int c = 0; c < 8; c++) {
            int ss = (tid >> 4) + c * 8;
            int dd = (tid & 15) * 4;
            const float* kp = base + 768  + (size_t)(kt * 64 + ss) * QKV3 + dd;
            const float* vp = base + 1536 + (size_t)(kt * 64 + ss) * QKV3 + dd;
            float4 k4 = *(const float4*)kp;
            float4 v4 = *(const float4*)vp;
            float ka[4] = {k4.x, k4.y, k4.z, k4.w};
            float va[4] = {v4.x, v4.y, v4.z, v4.w};
            #pragma unroll
            for (int j = 0; j < 4; j++) {
                int d = dd + j;
                Kf[((d >> 3) * 8 + (ss >> 3)) * 64 + ((((ss & 7) << 2) | (d & 3)) << 1) + ((d & 7) >> 2)]
                    = __uint_as_float(f2tf(ka[j]));
                Vf[((ss >> 3) * 8 + (d >> 3)) * 64 + ((((d & 7) << 2) | (ss & 3)) << 1) + ((ss & 7) >> 2)]
                    = __uint_as_float(f2tf(va[j]));
            }
        }
        __syncthreads();

        // ---- S = Q K^T (per warp: 16 x 64)
        float s[8][4];
        #pragma unroll
        for (int nj = 0; nj < 8; nj++)
            #pragma unroll
            for (int r = 0; r < 4; r++) s[nj][r] = 0.f;
        #pragma unroll
        for (int ks = 0; ks < 8; ks++) {
            #pragma unroll
            for (int nj = 0; nj < 8; nj++) {
                float2 kb = *(const float2*)&Kf[(ks * 8 + nj) * 64 + lane * 2];
                uint32_t bb[2] = {__float_as_uint(kb.x), __float_as_uint(kb.y)};
                mma8(s[nj], qf[ks], bb);
            }
        }

        // ---- online softmax (rows lr and lr+8 of warp strip)
        float mx0 = -INFINITY, mx1 = -INFINITY;
        #pragma unroll
        for (int nj = 0; nj < 8; nj++) {
            mx0 = fmaxf(mx0, fmaxf(s[nj][0], s[nj][1]));
            mx1 = fmaxf(mx1, fmaxf(s[nj][2], s[nj][3]));
        }
        mx0 = fmaxf(mx0, __shfl_xor_sync(0xffffffffu, mx0, 1));
        mx0 = fmaxf(mx0, __shfl_xor_sync(0xffffffffu, mx0, 2));
        mx1 = fmaxf(mx1, __shfl_xor_sync(0xffffffffu, mx1, 1));
        mx1 = fmaxf(mx1, __shfl_xor_sync(0xffffffffu, mx1, 2));
        float nm0 = fmaxf(m0r, mx0), nm1 = fmaxf(m1r, mx1);
        float al0 = __expf(m0r - nm0), al1 = __expf(m1r - nm1);
        m0r = nm0; m1r = nm1;
        float sum0 = 0.f, sum1 = 0.f;
        #pragma unroll
        for (int nj = 0; nj < 8; nj++) {
            float p0 = __expf(s[nj][0] - nm0);
            float p1 = __expf(s[nj][1] - nm0);
            float p2 = __expf(s[nj][2] - nm1);
            float p3 = __expf(s[nj][3] - nm1);
            sum0 += p0 + p1; sum1 += p2 + p3;
            int cb = nj * 8 + 2 * lc;
            // scatter P into A-fragment order: idx(r,c) =
            //   (c>>3)*128 + (((r&7)<<2)|(c&3))*4 + ((r>>3) + 2*((c&7)>>2))
            {
                int c0i = cb, c1i = cb + 1;
                Pw[nj * 128 + ((((lr) & 7) << 2 | (c0i & 3)) << 2) + (((c0i & 7) >> 2) << 1)]
                    = __uint_as_float(f2tf(p0));
                Pw[nj * 128 + ((((lr) & 7) << 2 | (c1i & 3)) << 2) + (((c1i & 7) >> 2) << 1)]
                    = __uint_as_float(f2tf(p1));
                Pw[nj * 128 + ((((lr) & 7) << 2 | (c0i & 3)) << 2) + 1 + (((c0i & 7) >> 2) << 1)]
                    = __uint_as_float(f2tf(p2));
                Pw[nj * 128 + ((((lr) & 7) << 2 | (c1i & 3)) << 2) + 1 + (((c1i & 7) >> 2) << 1)]
                    = __uint_as_float(f2tf(p3));
            }
        }
        sum0 += __shfl_xor_sync(0xffffffffu, sum0, 1);
        sum0 += __shfl_xor_sync(0xffffffffu, sum0, 2);
        sum1 += __shfl_xor_sync(0xffffffffu, sum1, 1);
        sum1 += __shfl_xor_sync(0xffffffffu, sum1, 2);
        l0 = l0 * al0 + sum0;
        l1 = l1 * al1 + sum1;
        #pragma unroll
        for (int nj = 0; nj < 8; nj++) {
            o[nj][0] *= al0; o[nj][1] *= al0;
            o[nj][2] *= al1; o[nj][3] *= al1;
        }
        __syncwarp();

        // ---- O += P V (per warp: 16 x 64)
        #pragma unroll
        for (int ks = 0; ks < 8; ks++) {
            float4 pa = *(const float4*)&Pw[ks * 128 + lane * 4];
            uint32_t aa[4] = {__float_as_uint(pa.x), __float_as_uint(pa.y),
                              __float_as_uint(pa.z), __float_as_uint(pa.w)};
            #pragma unroll
            for (int nj = 0; nj < 8; nj++) {
                float2 vb = *(const float2*)&Vf[(ks * 8 + nj) * 64 + lane * 2];
                uint32_t bb[2] = {__float_as_uint(vb.x), __float_as_uint(vb.y)};
                mma8(o[nj], aa, bb);
            }
        }
        __syncthreads();
    }

    // ---- normalize + write [B,T,H*D]
    float inv0 = 1.0f / l0, inv1 = 1.0f / l1;
    #pragma unroll
    for (int nj = 0; nj < 8; nj++) {
        int d = nj * 8 + 2 * lc;
        int row = r0 + q0w + lr;
        float* op = out + ((size_t)(b * T_ + row)) * C_ + h * D_ + d;
        *(float2*)op            = make_float2(o[nj][0] * inv0, o[nj][1] * inv0);
        *(float2*)(op + 8 * C_) = make_float2(o[nj][2] * inv1, o[nj][3] * inv1);
    }
}

// ---------------------------------------------------------------------------
extern "C" void kernel_launch(void* const* d_in, const int* in_sizes, int n_in,
                              void* d_out, int out_size)
{
    const float* x     = (const float*)d_in[0];
    const float* gamma = (const float*)d_in[1];
    const float* beta  = (const float*)d_in[2];
    const float* w_qkv = (const float*)d_in[3];
    const float* w_out = (const float*)d_in[4];
    const float* b_out = (const float*)d_in[5];
    float* out = (float*)d_out;

    float *xn, *qkv, *attn;
    cudaGetSymbolAddress((void**)&xn,   g_xn);
    cudaGetSymbolAddress((void**)&qkv,  g_qkv);
    cudaGetSymbolAddress((void**)&attn, g_attn);

    // 1) LayerNorm
    ln_kernel<<<B_ * T_, 256>>>(x, gamma, beta, xn);

    // 2) QKV projection (3xTF32, fp32-accurate)
    gemm_tf32x3<<<dim3(QKV3 / 128, (B_ * T_) / 128), 256>>>(
        xn, w_qkv, nullptr, qkv, B_ * T_, QKV3, C_);

    // 3) Flash attention (tf32 tensor cores, block-causal by frame)
    const int att_smem = 12288 * (int)sizeof(float);  // 48 KB
    cudaFuncSetAttribute(attn_tf32,
                         cudaFuncAttributeMaxDynamicSharedMemorySize, att_smem);
    attn_tf32<<<dim3(T_ / 64, B_ * H_), 128, att_smem>>>(qkv, attn);

    // 4) Output projection + bias (3xTF32)
    gemm_tf32x3<<<dim3(C_ / 128, (B_ * T_) / 128), 256>>>(
        attn, w_out, b_out, out, B_ * T_, C_, C_);
}